// round 8
// baseline (speedup 1.0000x reference)
#include <cuda_runtime.h>

// LIF scan: v = v + (x - v)*0.5; s = (v >= 1); v = s ? 0 : v
// x: [B=64, T=200, N=4096] fp32 -> spikes same shape.
//
// R8: R5 (float2, depth-1 pipeline, 28 warps/SM, 38 regs) with ONE change:
// streaming cache hints on both sides. Reads (__ldcs) and writes (__stcs)
// are single-touch; evict-first policy keeps L2 free to buffer the write
// stream, easing DRAM read/write turnaround — the identified limiter after
// occupancy (R7) and per-thread MLP (R4) were both falsified.

#define LIF_B 64
#define LIF_T 200
#define LIF_N 4096
#define NV2 (LIF_N / 2)      // 2048 float2 per (b, t) row
#define G 8                  // timesteps per group
#define NGROUP (LIF_T / G)   // 25

__device__ __forceinline__ void lif_step(float& v, float xx, float& s) {
    v = v + (xx - v) * 0.5f;          // exact match to ref op order (x0.5 exact)
    bool fire = (v >= 1.0f);
    s = fire ? 1.0f : 0.0f;
    v = fire ? 0.0f : v;
}

__device__ __forceinline__ void load_group(const float2* __restrict__ xp,
                                           float2 (&xr)[G]) {
    #pragma unroll
    for (int i = 0; i < G; i++) xr[i] = __ldcs(xp + i * NV2);
}

__device__ __forceinline__ void process_group(float2& v, const float2 (&xr)[G],
                                              float2* __restrict__ op) {
    #pragma unroll
    for (int i = 0; i < G; i++) {
        float2 s;
        lif_step(v.x, xr[i].x, s.x);
        lif_step(v.y, xr[i].y, s.y);
        __stcs(op + i * NV2, s);
    }
}

__global__ __launch_bounds__(64)
void lif_kernel(const float2* __restrict__ x, float2* __restrict__ out) {
    int idx = blockIdx.x * blockDim.x + threadIdx.x;   // 0 .. B*NV2-1
    int b   = idx >> 11;          // / NV2 (NV2 = 2048)
    int n2  = idx & (NV2 - 1);

    size_t base = (size_t)b * LIF_T * NV2 + n2;
    const float2* xp = x + base;
    float2*       op = out + base;

    float2 v = make_float2(0.f, 0.f);
    float2 xa[G], xb[G];

    // prologue: load group 0
    load_group(xp, xa);

    // 24 groups in 12 double-iterations; each half prefetches the next group
    // before touching the serial compute chain of the current one.
    #pragma unroll 1
    for (int gg = 0; gg < (NGROUP - 1) / 2; gg++) {
        load_group(xp + G * NV2, xb);        // prefetch group 2gg+1
        process_group(v, xa, op);            // compute+store group 2gg
        xp += G * NV2; op += G * NV2;

        load_group(xp + G * NV2, xa);        // prefetch group 2gg+2
        process_group(v, xb, op);            // compute+store group 2gg+1
        xp += G * NV2; op += G * NV2;
    }

    // epilogue: group 24 (already loaded into xa)
    process_group(v, xa, op);
}

extern "C" void kernel_launch(void* const* d_in, const int* in_sizes, int n_in,
                              void* d_out, int out_size) {
    const float* x = (const float*)d_in[0];
    // d_in[1] = threshold param, unused by the reference forward
    float* out = (float*)d_out;

    const int total_threads = LIF_B * NV2;   // 131072
    const int block = 64;
    lif_kernel<<<total_threads / block, block>>>(
        (const float2*)x, (float2*)out);
}

// round 9
// speedup vs baseline: 1.0689x; 1.0689x over previous
#include <cuda_runtime.h>

// LIF scan: v = v + (x - v)*0.5; s = (v >= 1); v = s ? 0 : v
// x: [B=64, T=200, N=4096] fp32 -> spikes same shape.
//
// R9: R5 structure (float2, depth-1 prefetch pipeline, 28 warps/SM, plain
// cached loads — streaming hints proven harmful in R8) with ONE change:
// group size G 8 -> 10. Deeper per-burst MLP (10 LDG.64 front-batched) and
// 20% fewer loop iterations; payload stays ~46 regs, far below the R4 cliff.

#define LIF_B 64
#define LIF_T 200
#define LIF_N 4096
#define NV2 (LIF_N / 2)      // 2048 float2 per (b, t) row
#define G 10                 // timesteps per group
#define NGROUP (LIF_T / G)   // 20

__device__ __forceinline__ void lif_step(float& v, float xx, float& s) {
    v = v + (xx - v) * 0.5f;          // exact match to ref op order (x0.5 exact)
    bool fire = (v >= 1.0f);
    s = fire ? 1.0f : 0.0f;
    v = fire ? 0.0f : v;
}

__device__ __forceinline__ void load_group(const float2* __restrict__ xp,
                                           float2 (&xr)[G]) {
    #pragma unroll
    for (int i = 0; i < G; i++) xr[i] = __ldg(xp + i * NV2);
}

__device__ __forceinline__ void process_group(float2& v, const float2 (&xr)[G],
                                              float2* __restrict__ op) {
    #pragma unroll
    for (int i = 0; i < G; i++) {
        float2 s;
        lif_step(v.x, xr[i].x, s.x);
        lif_step(v.y, xr[i].y, s.y);
        op[i * NV2] = s;
    }
}

__global__ __launch_bounds__(64)
void lif_kernel(const float2* __restrict__ x, float2* __restrict__ out) {
    int idx = blockIdx.x * blockDim.x + threadIdx.x;   // 0 .. B*NV2-1
    int b   = idx >> 11;          // / NV2 (NV2 = 2048)
    int n2  = idx & (NV2 - 1);

    size_t base = (size_t)b * LIF_T * NV2 + n2;
    const float2* xp = x + base;
    float2*       op = out + base;

    float2 v = make_float2(0.f, 0.f);
    float2 xa[G], xb[G];

    // prologue: load group 0
    load_group(xp, xa);

    // Groups 0..17 in 9 double-iterations, always prefetching one group ahead.
    #pragma unroll 1
    for (int gg = 0; gg < (NGROUP - 2) / 2; gg++) {
        load_group(xp + G * NV2, xb);        // prefetch group 2gg+1
        process_group(v, xa, op);            // compute+store group 2gg
        xp += G * NV2; op += G * NV2;

        load_group(xp + G * NV2, xa);        // prefetch group 2gg+2
        process_group(v, xb, op);            // compute+store group 2gg+1
        xp += G * NV2; op += G * NV2;
    }

    // Tail: group 18 (in xa), prefetch group 19, then process it.
    load_group(xp + G * NV2, xb);            // prefetch group 19
    process_group(v, xa, op);                // group 18
    op += G * NV2;
    process_group(v, xb, op);                // group 19
}

extern "C" void kernel_launch(void* const* d_in, const int* in_sizes, int n_in,
                              void* d_out, int out_size) {
    const float* x = (const float*)d_in[0];
    // d_in[1] = threshold param, unused by the reference forward
    float* out = (float*)d_out;

    const int total_threads = LIF_B * NV2;   // 131072
    const int block = 64;
    lif_kernel<<<total_threads / block, block>>>(
        (const float2*)x, (float2*)out);
}

// round 10
// speedup vs baseline: 1.0940x; 1.0235x over previous
#include <cuda_runtime.h>

// LIF scan: v = v + (x - v)*0.5; s = (v >= 1); v = s ? 0 : v
// x: [B=64, T=200, N=4096] fp32 -> spikes same shape.
//
// FINAL (R5 config): float2 granularity (131072 threads, ~28 warps/SM),
// depth-1 software pipeline over groups of 8 timesteps (8 front-batched
// LDG.64 per burst), plain cached loads, block=64 (13.8 CTAs/SM, ~1% wave
// imbalance), 38 regs.
//
// Optimization log: depth-2 pipelining (R4: reg cliff), 2x occupancy (R7:
// neutral), streaming cache hints (R8: regression), G=10 bursts (R9:
// neutral) all failed to move the 61.2us kernel plateau. Effective traffic
// 420 MB / 61.2 us = 6.86 TB/s = 86% of HBM3e spec for a 1:1 R/W mix --
// this is the memory-system ceiling for the pattern.

#define LIF_B 64
#define LIF_T 200
#define LIF_N 4096
#define NV2 (LIF_N / 2)      // 2048 float2 per (b, t) row
#define G 8                  // timesteps per group
#define NGROUP (LIF_T / G)   // 25

__device__ __forceinline__ void lif_step(float& v, float xx, float& s) {
    v = v + (xx - v) * 0.5f;          // exact match to ref op order (x0.5 exact)
    bool fire = (v >= 1.0f);
    s = fire ? 1.0f : 0.0f;
    v = fire ? 0.0f : v;
}

__device__ __forceinline__ void load_group(const float2* __restrict__ xp,
                                           float2 (&xr)[G]) {
    #pragma unroll
    for (int i = 0; i < G; i++) xr[i] = __ldg(xp + i * NV2);
}

__device__ __forceinline__ void process_group(float2& v, const float2 (&xr)[G],
                                              float2* __restrict__ op) {
    #pragma unroll
    for (int i = 0; i < G; i++) {
        float2 s;
        lif_step(v.x, xr[i].x, s.x);
        lif_step(v.y, xr[i].y, s.y);
        op[i * NV2] = s;
    }
}

__global__ __launch_bounds__(64)
void lif_kernel(const float2* __restrict__ x, float2* __restrict__ out) {
    int idx = blockIdx.x * blockDim.x + threadIdx.x;   // 0 .. B*NV2-1
    int b   = idx >> 11;          // / NV2 (NV2 = 2048)
    int n2  = idx & (NV2 - 1);

    size_t base = (size_t)b * LIF_T * NV2 + n2;
    const float2* xp = x + base;
    float2*       op = out + base;

    float2 v = make_float2(0.f, 0.f);
    float2 xa[G], xb[G];

    // prologue: load group 0
    load_group(xp, xa);

    // 24 groups in 12 double-iterations; each half prefetches the next group
    // before touching the serial compute chain of the current one.
    #pragma unroll 1
    for (int gg = 0; gg < (NGROUP - 1) / 2; gg++) {
        load_group(xp + G * NV2, xb);        // prefetch group 2gg+1
        process_group(v, xa, op);            // compute+store group 2gg
        xp += G * NV2; op += G * NV2;

        load_group(xp + G * NV2, xa);        // prefetch group 2gg+2
        process_group(v, xb, op);            // compute+store group 2gg+1
        xp += G * NV2; op += G * NV2;
    }

    // epilogue: group 24 (already loaded into xa)
    process_group(v, xa, op);
}

extern "C" void kernel_launch(void* const* d_in, const int* in_sizes, int n_in,
                              void* d_out, int out_size) {
    const float* x = (const float*)d_in[0];
    // d_in[1] = threshold param, unused by the reference forward
    float* out = (float*)d_out;

    const int total_threads = LIF_B * NV2;   // 131072
    const int block = 64;
    lif_kernel<<<total_threads / block, block>>>(
        (const float2*)x, (float2*)out);
}